// round 9
// baseline (speedup 1.0000x reference)
#include <cuda_runtime.h>
#include <cuda_bf16.h>
#include <cstdint>

#define T_STEPS 512
#define BATCH   128
#define EDIM    512
#define UDIM    1024
#define ZDIM    4096
#define VOCAB   50257
#define RB2     64        // k2 blocks
#define UPB     16        // u's per k2 block

// ---------------- device scratch (no allocation allowed) -------------------
__device__ uint32_t g_embb[(size_t)VOCAB * EDIM / 2];   // bf16x2 emb table
__device__ uint32_t g_wxT [(size_t)ZDIM * EDIM / 2];    // bf16x2 Wx^T [n][k]
__device__ float    g_xz[(size_t)T_STEPS * BATCH * ZDIM]; // fp32 [t][b][4U]
__device__ uint32_t g_hb[2][BATCH * UDIM / 2];          // bf16x2 hidden state
__device__ unsigned g_slab[8 * 32];                     // per-slab counters (padded)
__device__ int      g_is64;

// ---------------- helpers --------------------------------------------------
__device__ __forceinline__ uint32_t packbf(float lo, float hi){
    __nv_bfloat162 v = __floats2bfloat162_rn(lo, hi);
    return *(uint32_t*)&v;
}
__device__ __forceinline__ void mma16(float* c, const uint32_t* a, uint32_t b0, uint32_t b1){
    asm volatile("mma.sync.aligned.m16n8k16.row.col.f32.bf16.bf16.f32 "
        "{%0,%1,%2,%3},{%4,%5,%6,%7},{%8,%9},{%0,%1,%2,%3};"
        : "+f"(c[0]), "+f"(c[1]), "+f"(c[2]), "+f"(c[3])
        : "r"(a[0]), "r"(a[1]), "r"(a[2]), "r"(a[3]), "r"(b0), "r"(b1));
}
__device__ __forceinline__ void cp16(uint32_t s, const void* g){
    asm volatile("cp.async.cg.shared.global [%0], [%1], 16;" :: "r"(s), "l"(g));
}
__device__ __forceinline__ void cp_commit(){ asm volatile("cp.async.commit_group;"); }
__device__ __forceinline__ void cp_wait1(){ asm volatile("cp.async.wait_group 1;"); }
__device__ __forceinline__ void cp_wait0(){ asm volatile("cp.async.wait_group 0;"); }
__device__ __forceinline__ float sigf(float x){ return 1.f/(1.f + __expf(-x)); }
__device__ __forceinline__ unsigned ld_acq(const unsigned* p){
    unsigned v; asm volatile("ld.acquire.gpu.global.u32 %0,[%1];" : "=r"(v) : "l"(p)); return v;
}
__device__ __forceinline__ void poll_slab(int s, unsigned target){
    const unsigned* p = &g_slab[s*32];
    if (ld_acq(p) >= target) return;
    long long start = clock64();
    do {
        __nanosleep(32);
        if (clock64() - start > 2000000000LL) __trap();
    } while (ld_acq(p) < target);
}

// ---------------- init + prep ---------------------------------------------
__global__ void k_init(const int* __restrict__ s32){
    int i = blockIdx.x * blockDim.x + threadIdx.x;
    if (i < BATCH*UDIM/2) g_hb[0][i] = 0u;
    if (i < 8*32) g_slab[i] = 0u;
    if (i == 0){
        int is64 = 1;
        for (int j = 1; j < 512; j += 2) if (s32[j] != 0) { is64 = 0; break; }
        g_is64 = is64;
    }
}
__global__ void k_prep_emb(const float* __restrict__ emb){
    const size_t N = (size_t)VOCAB * EDIM / 2;
    const float2* e2 = (const float2*)emb;
    for (size_t i = blockIdx.x*blockDim.x + threadIdx.x; i < N; i += (size_t)gridDim.x*blockDim.x){
        float2 v = e2[i];
        g_embb[i] = packbf(v.x, v.y);
    }
}
__global__ void k_prep_wx(const float* __restrict__ Wx){
    const size_t N = (size_t)ZDIM * EDIM / 2;
    for (size_t i = blockIdx.x*blockDim.x + threadIdx.x; i < N; i += (size_t)gridDim.x*blockDim.x){
        int kp = (int)(i / ZDIM);
        int n  = (int)(i % ZDIM);
        float lo = Wx[(size_t)(2*kp)  *ZDIM + n];
        float hi = Wx[(size_t)(2*kp+1)*ZDIM + n];
        g_wxT[(size_t)n * (EDIM/2) + kp] = packbf(lo, hi);
    }
}

// ---------------- k1: fused embedding + (BT,E)x(E,4U) bf16 GEMM ------------
#define K1_AB   4608                      // u32 per buffer: 128 rows * 36
#define K1_SMEM ((4*K1_AB)*4 + 512)

__global__ __launch_bounds__(256,2) void k_xzgemm(
    const int* __restrict__ s32, const long long* __restrict__ s64,
    const float* __restrict__ bias)
{
    extern __shared__ uint32_t sm1[];
    uint32_t* As = sm1;
    uint32_t* Bs = sm1 + 2*K1_AB;
    int*     tok = (int*)(sm1 + 4*K1_AB);

    const int tid = threadIdx.x;
    const int lane = tid & 31, wid = tid >> 5;
    const int wm = wid & 3, wn = wid >> 2;
    const int gid = lane >> 2, tig = lane & 3;
    const int row0 = blockIdx.y * 128;
    const int col0 = blockIdx.x * 128;
    const int is64 = g_is64;

    if (tid < 128) tok[tid] = is64 ? (int)s64[row0 + tid] : s32[row0 + tid];
    __syncthreads();

    float acc[2][8][4];
    #pragma unroll
    for (int mt=0; mt<2; mt++)
        #pragma unroll
        for (int tl=0; tl<8; tl++)
            #pragma unroll
            for (int q=0; q<4; q++) acc[mt][tl][q] = 0.f;

    uint32_t sA = (uint32_t)__cvta_generic_to_shared(As);
    uint32_t sB = (uint32_t)__cvta_generic_to_shared(Bs);

    #define K1_ISSUE(s, buf) { \
        _Pragma("unroll") \
        for (int i=0; i<4; i++){ \
            int l = tid + i*256; int r_ = l >> 3, sg = l & 7; \
            cp16(sA + (uint32_t)(((buf)*K1_AB + r_*36 + sg*4)*4), \
                 g_embb + (size_t)tok[r_]*(EDIM/2) + (s)*32 + sg*4); \
        } \
        _Pragma("unroll") \
        for (int i=0; i<4; i++){ \
            int l = tid + i*256; int r_ = l >> 3, sg = l & 7; \
            cp16(sB + (uint32_t)(((buf)*K1_AB + r_*36 + sg*4)*4), \
                 g_wxT + (size_t)(col0 + r_)*(EDIM/2) + (s)*32 + sg*4); \
        } }

    K1_ISSUE(0, 0); cp_commit();
    for (int s=0; s<8; s++){
        if (s < 7){ K1_ISSUE(s+1, (s+1)&1); cp_commit(); cp_wait1(); }
        else cp_wait0();
        __syncthreads();
        const uint32_t* A = As + (s&1)*K1_AB;
        const uint32_t* B = Bs + (s&1)*K1_AB;
        #pragma unroll
        for (int cc=0; cc<4; cc++){
            uint32_t af[2][4];
            #pragma unroll
            for (int mt=0; mt<2; mt++){
                int row = wm*32 + mt*16 + gid;
                int base = row*36 + cc*8 + tig;
                af[mt][0] = A[base];
                af[mt][1] = A[base + 8*36];
                af[mt][2] = A[base + 4];
                af[mt][3] = A[base + 8*36 + 4];
            }
            #pragma unroll
            for (int tl=0; tl<8; tl++){
                int n = wn*64 + tl*8 + gid;
                int bb = n*36 + cc*8 + tig;
                uint32_t b0 = B[bb], b1 = B[bb + 4];
                mma16(acc[0][tl], af[0], b0, b1);
                mma16(acc[1][tl], af[1], b0, b1);
            }
        }
        __syncthreads();
    }
    #pragma unroll
    for (int mt=0; mt<2; mt++){
        #pragma unroll
        for (int tl=0; tl<8; tl++){
            int colg = col0 + wn*64 + tl*8 + tig*2;
            float bb0 = bias[colg], bb1 = bias[colg+1];
            #pragma unroll
            for (int p=0; p<2; p++){
                int rowg = row0 + wm*32 + mt*16 + gid + p*8; // = b*512 + t
                int bidx = rowg >> 9, tt = rowg & 511;
                float2 v;
                v.x = acc[mt][tl][p*2+0] + bb0;
                v.y = acc[mt][tl][p*2+1] + bb1;
                *(float2*)(g_xz + ((size_t)tt*BATCH + bidx)*ZDIM + colg) = v;
            }
        }
    }
}

// ---------------- k2: persistent LSTM recurrence (64 blocks x 16 u) --------
// Fine-grained per-slab sync; 8 warps; Wh slice (128 KB) SMEM-resident.
#define K2_WHS  32768     // u32: 4g x 16u x 1024k bf16
#define K2_SLAB 8704      // u32 per buffer: 128 rows * 68
#define K2_SMEM ((K2_WHS + 2*K2_SLAB)*4)   // ~200.7 KB -> 1 block/SM

__global__ __launch_bounds__(256,1) void k_lstm(const float* __restrict__ Wh)
{
    extern __shared__ uint32_t sm2[];
    uint32_t* whs = sm2;
    uint32_t* As  = sm2 + K2_WHS;

    const int tid = threadIdx.x;
    const int lane = tid & 31, w = tid >> 5;
    const int gid = lane >> 2, tig = lane & 3;
    const int u0 = blockIdx.x * UPB;
    const int sgrp = blockIdx.x >> 3;   // this block's h-slab group

    // Wh bf16 fragments: idx = (((kc*4+g)*2+v)*32 + lane)*2 + r
    for (int idx = tid; idx < K2_WHS; idx += 256){
        int r  = idx & 1;
        int l  = (idx >> 1) & 31;
        int v  = (idx >> 6) & 1;
        int g  = (idx >> 7) & 3;
        int kc = idx >> 9;                    // 0..63
        int k  = kc*16 + (l & 3)*2 + r*8;
        int col= g*1024 + u0 + v*8 + (l >> 2);
        whs[idx] = packbf(Wh[(size_t)k*ZDIM + col], Wh[(size_t)(k+1)*ZDIM + col]);
    }
    __syncthreads();

    float cst[8];
    #pragma unroll
    for (int i=0;i<8;i++) cst[i] = 0.f;

    uint32_t sA = (uint32_t)__cvta_generic_to_shared(As);

    // slab s covers k-pairs [s*64, s*64+64)
    #define K2_ISSUE(s, buf, hp) { \
        _Pragma("unroll") \
        for (int i=0;i<8;i++){ \
            int l = tid + i*256; int r_ = l >> 4, sg = l & 15; \
            cp16(sA + (uint32_t)(((buf)*K2_SLAB + r_*68 + sg*4)*4), \
                 (hp) + (size_t)r_*(UDIM/2) + (s)*64 + sg*4); \
        } }

    #define LDXZ(tt, dst) { \
        const float* xzp = g_xz + (size_t)(tt) * BATCH * ZDIM; \
        _Pragma("unroll") \
        for (int g=0; g<4; g++) \
          _Pragma("unroll") \
          for (int v=0; v<2; v++) \
            _Pragma("unroll") \
            for (int p=0; p<2; p++){ \
                int row = w*16 + gid + p*8; \
                float2 vv = *(const float2*)(xzp + (size_t)row*ZDIM + g*1024 + u0 + v*8 + tig*2); \
                dst[g][v][p*2+0] = vv.x; \
                dst[g][v][p*2+1] = vv.y; \
            } }

    float xzn[4][2][4];
    LDXZ(0, xzn);

    for (int t=0; t<T_STEPS; t++){
        const uint32_t* hin  = g_hb[t & 1];
        uint32_t*       hout = g_hb[(t+1) & 1];
        const unsigned  tgt  = (unsigned)t * 8u;

        float acc[4][2][4];
        #pragma unroll
        for (int g=0; g<4; g++)
            #pragma unroll
            for (int v=0; v<2; v++)
                #pragma unroll
                for (int q=0; q<4; q++) acc[g][v][q] = xzn[g][v][q];

        poll_slab(0, tgt);
        K2_ISSUE(0, 0, hin); cp_commit();

        for (int s=0; s<8; s++){
            if (s < 7) poll_slab(s+1, tgt);
            cp_wait0();
            __syncthreads();
            if (s < 7){ K2_ISSUE(s+1, (s+1)&1, hin); cp_commit(); }

            const uint32_t* A = As + (s & 1)*K2_SLAB;
            #pragma unroll
            for (int cc=0; cc<8; cc++){
                int kc = s*8 + cc;
                uint32_t af[4];
                int row = w*16 + gid;
                int base = row*68 + cc*8 + tig;
                af[0] = A[base];
                af[1] = A[base + 8*68];
                af[2] = A[base + 4];
                af[3] = A[base + 8*68 + 4];
                #pragma unroll
                for (int g=0; g<4; g++)
                    #pragma unroll
                    for (int v=0; v<2; v++){
                        uint2 bv = *(const uint2*)&whs[(((kc*4+g)*2+v)*32 + lane)*2];
                        mma16(acc[g][v], af, bv.x, bv.y);
                    }
            }
        }

        // prefetch next step's xz while gates compute
        if (t+1 < T_STEPS) LDXZ(t+1, xzn);

        // gates + state; write h bf16 pairs (4 stores/thread)
        #pragma unroll
        for (int v=0; v<2; v++)
            #pragma unroll
            for (int p=0; p<2; p++){
                float hq[2];
                #pragma unroll
                for (int q=0; q<2; q++){
                    int ci = v*4 + p*2 + q;
                    float iv = sigf(acc[0][v][p*2+q]);
                    float fv = sigf(acc[1][v][p*2+q]);
                    float gv = tanhf(acc[2][v][p*2+q]);
                    float ov = sigf(acc[3][v][p*2+q]);
                    float c  = fv*cst[ci] + iv*gv;
                    cst[ci]  = c;
                    hq[q] = ov * tanhf(c);
                }
                int row = w*16 + gid + p*8;
                hout[(size_t)row*(UDIM/2) + (u0>>1) + v*4 + tig] = packbf(hq[0], hq[1]);
            }

        __syncthreads();                 // all block stores done
        if (tid == 0){
            __threadfence();             // publish to L2 (gpu scope)
            atomicAdd(&g_slab[sgrp*32], 1u);
        }
    }
}

// ---------------- k3: head (256 thr, k-split x4) ---------------------------
__global__ void k_head(const float* __restrict__ W1, const float* __restrict__ b1,
                       const float* __restrict__ W2, const float* __restrict__ b2,
                       float* __restrict__ out)
{
    int b = blockIdx.x, t = threadIdx.x;
    int j = t & 63, kq = t >> 6;
    const uint32_t* h = g_hb[0] + (size_t)b*(UDIM/2);
    float s = 0.f;
    for (int kp = kq*128; kp < kq*128 + 128; kp++){
        uint32_t pr = h[kp];
        __nv_bfloat162 v = *(__nv_bfloat162*)&pr;
        s += __bfloat162float(v.x) * W1[(size_t)(2*kp)*64 + j]
           + __bfloat162float(v.y) * W1[(size_t)(2*kp+1)*64 + j];
    }
    __shared__ float red[256];
    red[t] = s;
    __syncthreads();
    float v = 0.f;
    if (t < 64){
        v = red[t] + red[t+64] + red[t+128] + red[t+192] + b1[t];
        v *= W2[t];
    }
    #pragma unroll
    for (int o=16; o>0; o>>=1) v += __shfl_down_sync(0xffffffffu, v, o);
    if (t == 0 || t == 32) red[t] = v;
    __syncthreads();
    if (t == 0) out[b] = 1.f/(1.f + __expf(-(red[0] + red[32] + b2[0])));
}

// ---------------- launch ---------------------------------------------------
extern "C" void kernel_launch(void* const* d_in, const int* in_sizes, int n_in,
                              void* d_out, int out_size)
{
    const int*       s32 = (const int*)d_in[0];
    const long long* s64 = (const long long*)d_in[0];
    const float* emb = (const float*)d_in[1];
    const float* Wx  = (const float*)d_in[2];
    const float* Wh  = (const float*)d_in[3];
    const float* b   = (const float*)d_in[4];
    const float* W1  = (const float*)d_in[5];
    const float* b1  = (const float*)d_in[6];
    const float* W2  = (const float*)d_in[7];
    const float* b2  = (const float*)d_in[8];
    float* out = (float*)d_out;

    cudaFuncSetAttribute(k_xzgemm, cudaFuncAttributeMaxDynamicSharedMemorySize, K1_SMEM);
    cudaFuncSetAttribute(k_lstm,   cudaFuncAttributeMaxDynamicSharedMemorySize, K2_SMEM);

    k_init<<<512, 256>>>(s32);
    k_prep_emb<<<8192, 256>>>(emb);
    k_prep_wx<<<2048, 256>>>(Wx);
    k_xzgemm<<<dim3(32, 512), 256, K1_SMEM>>>(s32, s64, b);
    k_lstm<<<RB2, 256, K2_SMEM>>>(Wh);
    k_head<<<BATCH, 256>>>(W1, b1, W2, b2, out);
}

// round 11
// speedup vs baseline: 1.4890x; 1.4890x over previous
#include <cuda_runtime.h>
#include <cuda_bf16.h>
#include <cstdint>

#define T_STEPS 512
#define BATCH   128
#define EDIM    512
#define UDIM    1024
#define ZDIM    4096
#define VOCAB   50257
#define RB      128

// ---------------- device scratch (no allocation allowed) -------------------
__device__ uint32_t g_embb[(size_t)VOCAB * EDIM / 2];   // bf16x2 emb table
__device__ uint32_t g_wxT [(size_t)ZDIM * EDIM / 2];    // bf16x2 Wx^T [n][k]
__device__ float    g_xz[(size_t)T_STEPS * BATCH * ZDIM]; // fp32 [t][b][4U]
__device__ uint32_t g_hb[2][BATCH * UDIM / 2];          // bf16x2 hidden state
__device__ unsigned g_bar;
__device__ int      g_is64;

// ---------------- helpers --------------------------------------------------
__device__ __forceinline__ uint32_t packbf(float lo, float hi){
    __nv_bfloat162 v = __floats2bfloat162_rn(lo, hi);
    return *(uint32_t*)&v;
}
__device__ __forceinline__ void mma16(float* c, const uint32_t* a, uint32_t b0, uint32_t b1){
    asm volatile("mma.sync.aligned.m16n8k16.row.col.f32.bf16.bf16.f32 "
        "{%0,%1,%2,%3},{%4,%5,%6,%7},{%8,%9},{%0,%1,%2,%3};"
        : "+f"(c[0]), "+f"(c[1]), "+f"(c[2]), "+f"(c[3])
        : "r"(a[0]), "r"(a[1]), "r"(a[2]), "r"(a[3]), "r"(b0), "r"(b1));
}
__device__ __forceinline__ void ldsm4(uint32_t* r, uint32_t addr){
    asm volatile("ldmatrix.sync.aligned.m8n8.x4.shared.b16 {%0,%1,%2,%3}, [%4];"
        : "=r"(r[0]), "=r"(r[1]), "=r"(r[2]), "=r"(r[3]) : "r"(addr));
}
__device__ __forceinline__ void cp16(uint32_t s, const void* g){
    asm volatile("cp.async.cg.shared.global [%0], [%1], 16;" :: "r"(s), "l"(g));
}
__device__ __forceinline__ void cp_commit(){ asm volatile("cp.async.commit_group;"); }
__device__ __forceinline__ void cp_wait1(){ asm volatile("cp.async.wait_group 1;"); }
__device__ __forceinline__ void cp_wait0(){ asm volatile("cp.async.wait_group 0;"); }
__device__ __forceinline__ float sigf(float x){ return 1.f/(1.f + __expf(-x)); }

// ---------------- init + prep ---------------------------------------------
__global__ void k_init(const int* __restrict__ s32){
    int i = blockIdx.x * blockDim.x + threadIdx.x;
    if (i < BATCH*UDIM/2) g_hb[0][i] = 0u;
    if (i == 0){
        g_bar = 0u;
        int is64 = 1;
        for (int j = 1; j < 512; j += 2) if (s32[j] != 0) { is64 = 0; break; }
        g_is64 = is64;
    }
}
__global__ void k_prep_emb(const float* __restrict__ emb){
    const size_t N = (size_t)VOCAB * EDIM / 2;
    const float2* e2 = (const float2*)emb;
    for (size_t i = blockIdx.x*blockDim.x + threadIdx.x; i < N; i += (size_t)gridDim.x*blockDim.x){
        float2 v = e2[i];
        g_embb[i] = packbf(v.x, v.y);
    }
}
__global__ void k_prep_wx(const float* __restrict__ Wx){
    const size_t N = (size_t)ZDIM * EDIM / 2;
    for (size_t i = blockIdx.x*blockDim.x + threadIdx.x; i < N; i += (size_t)gridDim.x*blockDim.x){
        int kp = (int)(i / ZDIM);
        int n  = (int)(i % ZDIM);
        float lo = Wx[(size_t)(2*kp)  *ZDIM + n];
        float hi = Wx[(size_t)(2*kp+1)*ZDIM + n];
        g_wxT[(size_t)n * (EDIM/2) + kp] = packbf(lo, hi);
    }
}

// ---------------- k1: fused embedding + (BT,E)x(E,4U) bf16 GEMM ------------
#define K1_AB   4608                      // u32 per buffer: 128 rows * 36
#define K1_SMEM ((4*K1_AB)*4 + 512)

__global__ __launch_bounds__(256,2) void k_xzgemm(
    const int* __restrict__ s32, const long long* __restrict__ s64,
    const float* __restrict__ bias)
{
    extern __shared__ uint32_t sm1[];
    uint32_t* As = sm1;
    uint32_t* Bs = sm1 + 2*K1_AB;
    int*     tok = (int*)(sm1 + 4*K1_AB);

    const int tid = threadIdx.x;
    const int lane = tid & 31, wid = tid >> 5;
    const int wm = wid & 3, wn = wid >> 2;
    const int gid = lane >> 2, tig = lane & 3;
    const int lrow = lane & 7, lm = lane >> 3;      // ldmatrix row / matrix id
    const int row0 = blockIdx.y * 128;
    const int col0 = blockIdx.x * 128;
    const int is64 = g_is64;

    if (tid < 128) tok[tid] = is64 ? (int)s64[row0 + tid] : s32[row0 + tid];
    __syncthreads();

    float acc[2][8][4];
    #pragma unroll
    for (int mt=0; mt<2; mt++)
        #pragma unroll
        for (int tl=0; tl<8; tl++)
            #pragma unroll
            for (int q=0; q<4; q++) acc[mt][tl][q] = 0.f;

    uint32_t sA = (uint32_t)__cvta_generic_to_shared(As);
    uint32_t sB = (uint32_t)__cvta_generic_to_shared(Bs);

    // ldmatrix per-lane offsets (u32 units)
    int aoffA[2], boffB[4];
    #pragma unroll
    for (int mt=0; mt<2; mt++)
        aoffA[mt] = (wm*32 + mt*16 + (lm&1)*8 + lrow)*36 + (lm>>1)*4;
    #pragma unroll
    for (int j=0; j<4; j++)
        boffB[j] = (wn*64 + (2*j + (lm>>1))*8 + lrow)*36 + (lm&1)*4;

    #define K1_ISSUE(s, buf) { \
        _Pragma("unroll") \
        for (int i=0; i<4; i++){ \
            int l = tid + i*256; int r_ = l >> 3, sg = l & 7; \
            cp16(sA + (uint32_t)(((buf)*K1_AB + r_*36 + sg*4)*4), \
                 g_embb + (size_t)tok[r_]*(EDIM/2) + (s)*32 + sg*4); \
        } \
        _Pragma("unroll") \
        for (int i=0; i<4; i++){ \
            int l = tid + i*256; int r_ = l >> 3, sg = l & 7; \
            cp16(sB + (uint32_t)(((buf)*K1_AB + r_*36 + sg*4)*4), \
                 g_wxT + (size_t)(col0 + r_)*(EDIM/2) + (s)*32 + sg*4); \
        } }

    K1_ISSUE(0, 0); cp_commit();
    for (int s=0; s<8; s++){
        if (s < 7){ K1_ISSUE(s+1, (s+1)&1); cp_commit(); cp_wait1(); }
        else cp_wait0();
        __syncthreads();
        uint32_t aB = sA + (uint32_t)(((s&1)*K1_AB)*4);
        uint32_t bB = sB + (uint32_t)(((s&1)*K1_AB)*4);
        #pragma unroll
        for (int cc=0; cc<4; cc++){
            uint32_t afm[2][4];
            ldsm4(afm[0], aB + (uint32_t)((aoffA[0] + cc*8)*4));
            ldsm4(afm[1], aB + (uint32_t)((aoffA[1] + cc*8)*4));
            #pragma unroll
            for (int j=0; j<4; j++){
                uint32_t bf[4];
                ldsm4(bf, bB + (uint32_t)((boffB[j] + cc*8)*4));
                mma16(acc[0][2*j],   afm[0], bf[0], bf[1]);
                mma16(acc[0][2*j+1], afm[0], bf[2], bf[3]);
                mma16(acc[1][2*j],   afm[1], bf[0], bf[1]);
                mma16(acc[1][2*j+1], afm[1], bf[2], bf[3]);
            }
        }
        __syncthreads();
    }
    #pragma unroll
    for (int mt=0; mt<2; mt++){
        #pragma unroll
        for (int tl=0; tl<8; tl++){
            int colg = col0 + wn*64 + tl*8 + tig*2;
            float bb0 = bias[colg], bb1 = bias[colg+1];
            #pragma unroll
            for (int p=0; p<2; p++){
                int rowg = row0 + wm*32 + mt*16 + gid + p*8; // = b*512 + t
                int bidx = rowg >> 9, tt = rowg & 511;
                float2 v;
                v.x = acc[mt][tl][p*2+0] + bb0;
                v.y = acc[mt][tl][p*2+1] + bb1;
                *(float2*)(g_xz + ((size_t)tt*BATCH + bidx)*ZDIM + colg) = v;
            }
        }
    }
}

// ---------------- k2: persistent LSTM recurrence (128 blk x 8 warps) -------
// Block owns 8 u's (4 gates x n8). Wh repacked [g][n][k-pair] stride 524
// for conflict-free ldmatrix. h slabs: 128 rows x 64 pairs, stride 68.
#define K2_WHS  16768     // u32: 32 rows * 524
#define K2_SLAB 8704      // u32: 128 rows * 68
#define K2_SMEM ((K2_WHS + 2*K2_SLAB)*4)   // ~133.5 KB -> 1 block/SM

__global__ __launch_bounds__(256,1) void k_lstm(const float* __restrict__ Wh)
{
    extern __shared__ uint32_t sm2[];
    uint32_t* whs = sm2;
    uint32_t* As  = sm2 + K2_WHS;

    const int tid = threadIdx.x;
    const int lane = tid & 31, w = tid >> 5;
    const int gid = lane >> 2, tig = lane & 3;
    const int lrow = lane & 7, lm = lane >> 3;
    const int u0 = blockIdx.x * 8;

    // whs[(g*8+n)*524 + p] = pair p of Wh column (g*1024+u0+n)
    for (int idx = tid; idx < 16384; idx += 256){
        int p = idx & 511;
        int n = (idx >> 9) & 7;
        int g = idx >> 12;
        int col = g*1024 + u0 + n;
        whs[(g*8+n)*524 + p] =
            packbf(Wh[(size_t)(2*p)*ZDIM + col], Wh[(size_t)(2*p+1)*ZDIM + col]);
    }
    __syncthreads();

    float cst[4];
    #pragma unroll
    for (int i=0;i<4;i++) cst[i] = 0.f;

    uint32_t sA = (uint32_t)__cvta_generic_to_shared(As);
    uint32_t sW = (uint32_t)__cvta_generic_to_shared(whs);

    // ldmatrix per-lane offsets (u32 units)
    const int aoff  = (w*16 + (lm&1)*8 + lrow)*68 + (lm>>1)*4;
    const int boff0 = (((lm>>1))*8 + lrow)*524 + (lm&1)*4;       // gates 0/1
    const int boff1 = ((2 + (lm>>1))*8 + lrow)*524 + (lm&1)*4;   // gates 2/3

    #define K2_ISSUE(s, buf, hp) { \
        _Pragma("unroll") \
        for (int i=0;i<8;i++){ \
            int l = tid + i*256; int r_ = l >> 4, sg = l & 15; \
            cp16(sA + (uint32_t)(((buf)*K2_SLAB + r_*68 + sg*4)*4), \
                 (hp) + (size_t)r_*(UDIM/2) + (s)*64 + sg*4); \
        } }

    #define LDXZ(tt, dst) { \
        const float* xzp = g_xz + (size_t)(tt) * BATCH * ZDIM; \
        _Pragma("unroll") \
        for (int g=0; g<4; g++) \
            _Pragma("unroll") \
            for (int p=0; p<2; p++){ \
                int row = w*16 + gid + p*8; \
                float2 vv = *(const float2*)(xzp + (size_t)row*ZDIM + g*1024 + u0 + tig*2); \
                dst[g][p*2+0] = vv.x; \
                dst[g][p*2+1] = vv.y; \
            } }

    float xzn[4][4];
    LDXZ(0, xzn);

    for (int t=0; t<T_STEPS; t++){
        const uint32_t* hin  = g_hb[t & 1];
        uint32_t*       hout = g_hb[(t+1) & 1];

        K2_ISSUE(0, 0, hin); cp_commit();

        float acc[4][4];
        #pragma unroll
        for (int g=0; g<4; g++)
            #pragma unroll
            for (int q=0; q<4; q++) acc[g][q] = xzn[g][q];

        for (int s=0; s<8; s++){
            if (s < 7){ K2_ISSUE(s+1, (s+1)&1, hin); cp_commit(); cp_wait1(); }
            else cp_wait0();
            __syncthreads();

            uint32_t aB = sA + (uint32_t)(((s&1)*K2_SLAB)*4);
            #pragma unroll
            for (int cc=0; cc<8; cc++){
                int kc = s*8 + cc;
                uint32_t af[4];
                ldsm4(af, aB + (uint32_t)((aoff + cc*8)*4));
                uint32_t b01[4], b23[4];
                ldsm4(b01, sW + (uint32_t)((boff0 + kc*8)*4));
                mma16(acc[0], af, b01[0], b01[1]);
                mma16(acc[1], af, b01[2], b01[3]);
                ldsm4(b23, sW + (uint32_t)((boff1 + kc*8)*4));
                mma16(acc[2], af, b23[0], b23[1]);
                mma16(acc[3], af, b23[2], b23[3]);
            }
            __syncthreads();
        }

        // prefetch next step's xz while gates + barrier run
        if (t+1 < T_STEPS) LDXZ(t+1, xzn);

        // gates + state; write h bf16 pairs
        #pragma unroll
        for (int p=0; p<2; p++){
            float hq[2];
            #pragma unroll
            for (int q=0; q<2; q++){
                int ci = p*2 + q;
                float iv = sigf(acc[0][p*2+q]);
                float fv = sigf(acc[1][p*2+q]);
                float gv = tanhf(acc[2][p*2+q]);
                float ov = sigf(acc[3][p*2+q]);
                float c  = fv*cst[ci] + iv*gv;
                cst[ci]  = c;
                hq[q] = ov * tanhf(c);
            }
            int row = w*16 + gid + p*8;
            hout[(size_t)row*(UDIM/2) + (u0>>1) + tig] = packbf(hq[0], hq[1]);
        }

        // grid barrier (monotonic counter, nanosleep back-off, deadlock trap)
        __syncthreads();
        if (tid == 0){
            __threadfence();
            atomicAdd(&g_bar, 1u);
            unsigned target = (unsigned)(t+1) * RB;
            long long start = clock64();
            while (*(volatile unsigned*)&g_bar < target){
                __nanosleep(32);
                if (clock64() - start > 4000000000LL) __trap();
            }
            __threadfence();
        }
        __syncthreads();
    }
}

// ---------------- k3: head (256 thr, k-split x4) ---------------------------
__global__ void k_head(const float* __restrict__ W1, const float* __restrict__ b1,
                       const float* __restrict__ W2, const float* __restrict__ b2,
                       float* __restrict__ out)
{
    int b = blockIdx.x, t = threadIdx.x;
    int j = t & 63, kq = t >> 6;
    const uint32_t* h = g_hb[0] + (size_t)b*(UDIM/2);
    float s = 0.f;
    for (int kp = kq*128; kp < kq*128 + 128; kp++){
        uint32_t pr = h[kp];
        __nv_bfloat162 v = *(__nv_bfloat162*)&pr;
        s += __bfloat162float(v.x) * W1[(size_t)(2*kp)*64 + j]
           + __bfloat162float(v.y) * W1[(size_t)(2*kp+1)*64 + j];
    }
    __shared__ float red[256];
    red[t] = s;
    __syncthreads();
    float v = 0.f;
    if (t < 64){
        v = red[t] + red[t+64] + red[t+128] + red[t+192] + b1[t];
        v *= W2[t];
    }
    #pragma unroll
    for (int o=16; o>0; o>>=1) v += __shfl_down_sync(0xffffffffu, v, o);
    if (t == 0 || t == 32) red[t] = v;
    __syncthreads();
    if (t == 0) out[b] = 1.f/(1.f + __expf(-(red[0] + red[32] + b2[0])));
}

// ---------------- launch ---------------------------------------------------
extern "C" void kernel_launch(void* const* d_in, const int* in_sizes, int n_in,
                              void* d_out, int out_size)
{
    const int*       s32 = (const int*)d_in[0];
    const long long* s64 = (const long long*)d_in[0];
    const float* emb = (const float*)d_in[1];
    const float* Wx  = (const float*)d_in[2];
    const float* Wh  = (const float*)d_in[3];
    const float* b   = (const float*)d_in[4];
    const float* W1  = (const float*)d_in[5];
    const float* b1  = (const float*)d_in[6];
    const float* W2  = (const float*)d_in[7];
    const float* b2  = (const float*)d_in[8];
    float* out = (float*)d_out;

    cudaFuncSetAttribute(k_xzgemm, cudaFuncAttributeMaxDynamicSharedMemorySize, K1_SMEM);
    cudaFuncSetAttribute(k_lstm,   cudaFuncAttributeMaxDynamicSharedMemorySize, K2_SMEM);

    k_init<<<512, 256>>>(s32);
    k_prep_emb<<<8192, 256>>>(emb);
    k_prep_wx<<<2048, 256>>>(Wx);
    k_xzgemm<<<dim3(32, 512), 256, K1_SMEM>>>(s32, s64, b);
    k_lstm<<<RB, 256, K2_SMEM>>>(Wh);
    k_head<<<BATCH, 256>>>(W1, b1, W2, b2, out);
}